// round 16
// baseline (speedup 1.0000x reference)
#include <cuda_runtime.h>
#include <cuda_bf16.h>

#define BN 64
#define SEQ 48
#define HD 256
#define MM 193
#define TSTEPS 96

// ------------- device scratch -------------
__device__ float g_B [BN*SEQ*HD];
__device__ float g_sb[BN*SEQ];
__device__ float g_V [BN*MM*HD];
__device__ float g_s [BN*MM];
__device__ float g_c [BN*HD];
__device__ float g_ar[BN];
__device__ __align__(16) __nv_bfloat16 g_Wfh[1024*1024], g_Wfl[1024*1024];
__device__ __align__(16) __nv_bfloat16 g_Wth[1280*512],  g_Wtl[1280*512];
__device__ __align__(16) __nv_bfloat16 g_Wm0h[1024*256], g_Wm0l[1024*256];
__device__ __align__(16) __nv_bfloat16 g_Wm1h[1024*1024], g_Wm1l[1024*1024];
__device__ __align__(16) __nv_bfloat16 g_Aph [512*128], g_Apl [512*128];
__device__ __align__(16) __nv_bfloat16 g_A2ph[256*128], g_A2pl[256*128];
__device__ float g_r12[BN*512];
__device__ float g_bf[1024];
__device__ float g_bt[1280];
__device__ float g_Gp[8*BN*1024];
__device__ float g_Tp[4*BN*1280];
__device__ float g_y1[BN*1024];
__device__ int   g_is64;
__device__ unsigned g_cntL;
__device__ unsigned g_cntT;

__device__ __forceinline__ float sigf(float x){ return 1.f/(1.f+expf(-x)); }

__device__ __forceinline__ void packAct(__nv_bfloat16* Ah, __nv_bfloat16* Al,
                                        int k, int b, float v){
  __nv_bfloat16 hi = __float2bfloat16(v);
  float lo = v - __bfloat162float(hi);
  int idx = (k >> 1)*128 + 2*b + (k & 1);
  Ah[idx] = hi;
  Al[idx] = __float2bfloat16(lo);
}

#define MMA_BF16(D, A0,A1,A2,A3, B0,B1) \
  asm volatile("mma.sync.aligned.m16n8k16.row.col.f32.bf16.bf16.f32 " \
      "{%0,%1,%2,%3}, {%4,%5,%6,%7}, {%8,%9}, {%0,%1,%2,%3};" \
      : "+f"(D[0]),"+f"(D[1]),"+f"(D[2]),"+f"(D[3]) \
      : "r"(A0),"r"(A1),"r"(A2),"r"(A3),"r"(B0),"r"(B1))

#define CP16(dst, src) \
  asm volatile("cp.async.cg.shared.global [%0], [%1], 16;" :: "r"(dst), "l"(src))

// ------------- producer/consumer helpers -------------
__device__ __forceinline__ void prod_signal(unsigned* cnt){
  __threadfence();
  __syncthreads();
  if (threadIdx.x == 0) atomicAdd(cnt, 1u);
}
__device__ __forceinline__ void cons_wait(unsigned* cnt, unsigned target){
  if (threadIdx.x == 0){
    while (*(volatile unsigned*)cnt < target){ __nanosleep(32); }
  }
  __syncthreads();
  __threadfence();   // acquire: invalidate L1 so partial reads are fresh
}

// ------------- warp scans -------------
__device__ __forceinline__ void scan_stack_pop(float* srow, float a,
                                               float* w1, float* wt, float* w2x,
                                               int* mEnd, int* m2End){
  int lane = threadIdx.x & 31;
  float run = 0.f;
  #pragma unroll
  for (int c = 0; c < 7; c++){
    int m = c*32 + lane;
    float sv = (m < MM) ? srow[m] : 0.f;
    float v = sv;
    #pragma unroll
    for (int o = 1; o < 32; o <<= 1){
      float n = __shfl_up_sync(0xffffffffu, v, o);
      if (lane >= o) v += n;
    }
    float Pm = run + v, Pp = Pm - sv;
    float u1 = fminf(Pm, a) - fminf(Pp, a);
    float ut = fminf(Pm, 1.f + a) - fminf(Pp, 1.f + a);
    float Qm = fmaxf(0.f, Pm - (1.f + a));
    float Qp = fmaxf(0.f, Pp - (1.f + a));
    float u2 = fminf(Qm, 1.f) - fminf(Qp, 1.f);
    if (m < MM){
      w1[m] = u1; wt[m] = ut; w2x[m] = u2;
      srow[m] = sv - ut;
      if (ut > 0.f) atomicMax(mEnd, m + 1);
      if (u2 > 0.f) atomicMax(m2End, m + 1);
    }
    run += __shfl_sync(0xffffffffu, v, 31);
  }
  __syncwarp();
}

__device__ __forceinline__ void scan_buf_pop(float* srow, float a,
                                             float* wb, float* wbx,
                                             int* bEnd, int* bxEnd){
  int lane = threadIdx.x & 31;
  float run = 0.f;
  #pragma unroll
  for (int c = 0; c < 2; c++){
    int m = c*32 + lane;
    float sv = (m < SEQ) ? srow[m] : 0.f;
    float v = sv;
    #pragma unroll
    for (int o = 1; o < 32; o <<= 1){
      float n = __shfl_up_sync(0xffffffffu, v, o);
      if (lane >= o) v += n;
    }
    float Pm = run + v, Pp = Pm - sv;
    float w = fminf(Pm, a) - fminf(Pp, a);
    float Qm = fmaxf(0.f, Pm - a);
    float Qp = fmaxf(0.f, Pp - a);
    float wx = fminf(Qm, 1.f) - fminf(Qp, 1.f);
    if (m < SEQ){
      wb[m] = w; wbx[m] = wx;
      srow[m] = sv - w;
      if (w  > 0.f) atomicMax(bEnd,  m + 1);
      if (wx > 0.f) atomicMax(bxEnd, m + 1);
    }
    run += __shfl_sync(0xffffffffu, v, 31);
  }
  __syncwarp();
}

__device__ __forceinline__ void scan_buf(float* srow, float a, float* wb, int* bEnd){
  int lane = threadIdx.x & 31;
  float run = 0.f;
  #pragma unroll
  for (int c = 0; c < 2; c++){
    int m = c*32 + lane;
    float sv = (m < SEQ) ? srow[m] : 0.f;
    float v = sv;
    #pragma unroll
    for (int o = 1; o < 32; o <<= 1){
      float n = __shfl_up_sync(0xffffffffu, v, o);
      if (lane >= o) v += n;
    }
    float Pm = run + v, Pp = Pm - sv;
    float w = fminf(Pm, a) - fminf(Pp, a);
    if (m < SEQ){
      wb[m] = w;
      if (w > 0.f) atomicMax(bEnd, m + 1);
    }
    run += __shfl_sync(0xffffffffu, v, 31);
  }
  __syncwarp();
}

// ------------- token dtype detect -------------
__global__ void k_tok(const void* x){
  __shared__ int ok;
  if (threadIdx.x == 0) ok = 1;
  __syncthreads();
  const long long* xl = (const long long*)x;
  int bad = 0;
  for (int i = threadIdx.x; i < (BN*SEQ)/2; i += 256){
    long long v = xl[i];
    if (v < 0 || v >= 50257) bad = 1;
  }
  if (bad) atomicAnd(&ok, 0);
  __syncthreads();
  if (threadIdx.x == 0) g_is64 = ok;
}

// ------------- prep -------------
__global__ void k_prep(const void* x, const float* emb,
                       const float* wih, const float* whh,
                       const float* bih, const float* bhh,
                       const float* lw, const float* lb,
                       const float* rw, const float* rb,
                       const float* l0w, const float* l1w){
  cudaGridDependencySynchronize();
  int gid = blockIdx.x*blockDim.x + threadIdx.x;
  int gsz = gridDim.x*blockDim.x;
  if (gid == 0){ g_cntL = 0u; g_cntT = 0u; }
  int is64 = g_is64;
  const long long* xl = (const long long*)x;
  const int* xi = (const int*)x;
  for (int i = gid; i < BN*SEQ; i += gsz){
    long long tok = is64 ? xl[i] : (long long)xi[i];
    g_sb[i] = (tok > 0) ? 1.f : 0.f;
  }
  for (int i = gid; i < BN*SEQ*HD; i += gsz){
    int row = i >> 8;
    long long tok = is64 ? xl[row] : (long long)xi[row];
    g_B[i] = emb[(size_t)tok*HD + (i & 255)];
  }
  for (int i = gid; i < 1024*1024; i += gsz){
    int j = i >> 10, k = i & 1023;
    float wv = (k < 768) ? wih[j*768 + k] : whh[j*256 + (k-768)];
    __nv_bfloat16 hi = __float2bfloat16(wv);
    g_Wfh[i] = hi;
    g_Wfl[i] = __float2bfloat16(wv - __bfloat162float(hi));
  }
  for (int i = gid; i < 1280*512; i += gsz){
    int j = i >> 9, k = i & 511;
    float wv = (k < 256) ? lw[j*256 + k] : rw[j*256 + (k-256)];
    __nv_bfloat16 hi = __float2bfloat16(wv);
    g_Wth[i] = hi;
    g_Wtl[i] = __float2bfloat16(wv - __bfloat162float(hi));
  }
  for (int i = gid; i < 1024*256; i += gsz){
    float wv = l0w[i];
    __nv_bfloat16 hi = __float2bfloat16(wv);
    g_Wm0h[i] = hi;
    g_Wm0l[i] = __float2bfloat16(wv - __bfloat162float(hi));
  }
  for (int i = gid; i < 1024*1024; i += gsz){
    float wv = l1w[i];
    __nv_bfloat16 hi = __float2bfloat16(wv);
    g_Wm1h[i] = hi;
    g_Wm1l[i] = __float2bfloat16(wv - __bfloat162float(hi));
  }
  for (int i = gid; i < 1024; i += gsz) g_bf[i] = bih[i] + bhh[i];
  for (int i = gid; i < 1280; i += gsz) g_bt[i] = lb[i] + rb[i];
  for (int i = gid; i < BN*MM*HD; i += gsz) g_V[i] = 0.f;
  for (int i = gid; i < BN*MM; i += gsz) g_s[i] = 0.f;
  for (int i = gid; i < BN*HD; i += gsz) g_c[i] = 0.f;
  __nv_bfloat16 z = __float2bfloat16(0.f);
  for (int i = gid; i < 512*128; i += gsz){ g_Aph[i] = z; g_Apl[i] = z; }
  for (int i = gid; i < 256*128; i += gsz){ g_A2ph[i] = z; g_A2pl[i] = z; }
}

// ------------- cp.async 3-stage bf16 MMA GEMM (2-split compensated) -------------
#define STG_B 19456
template<int J, int K, int NKS>
__device__ __forceinline__ void gemm_cp(const __nv_bfloat16* __restrict__ Wh,
                                        const __nv_bfloat16* __restrict__ Wl,
                                        const __nv_bfloat16* __restrict__ Bh,
                                        const __nv_bfloat16* __restrict__ Bl,
                                        float* __restrict__ P){
  constexpr int KSL = K / NKS;
  constexpr int NCH = KSL / 32;
  extern __shared__ __nv_bfloat16 smem[];
  const int jt = blockIdx.x / NKS, ks = blockIdx.x % NKS;
  const int j0 = jt*64, k0 = ks*KSL;
  const int tid = threadIdx.x;
  const int w = tid >> 5, l = tid & 31, g = l >> 2, qi = l & 3;
  const int jw = (w & 3)*16, bw = (w >> 2)*32;
  const int jrow = tid >> 2, kq = tid & 3;
  const int brow = tid >> 4, bo = tid & 15;

  const __nv_bfloat16* gWh = Wh + (size_t)(j0 + jrow)*K + k0 + kq*8;
  const __nv_bfloat16* gWl = Wl + (size_t)(j0 + jrow)*K + k0 + kq*8;
  const __nv_bfloat16* gBh = Bh + (size_t)(k0/2 + brow)*128 + bo*8;
  const __nv_bfloat16* gBl = Bl + (size_t)(k0/2 + brow)*128 + bo*8;

  const unsigned sbase = (unsigned)__cvta_generic_to_shared(smem);
  const unsigned wOff = (jrow*40 + kq*8)*2;
  const unsigned bOff = (brow*144 + bo*8)*2;

  float d[4][4];
  #pragma unroll
  for (int i = 0; i < 4; i++)
    #pragma unroll
    for (int j = 0; j < 4; j++) d[i][j] = 0.f;

  #pragma unroll
  for (int cc = 0; cc < 2; cc++){
    unsigned sb = sbase + cc*STG_B;
    CP16(sb + wOff,          gWh + cc*32);
    CP16(sb + 5120 + wOff,   gWl + cc*32);
    CP16(sb + 10240 + bOff,  gBh + (size_t)cc*2048);
    CP16(sb + 14848 + bOff,  gBl + (size_t)cc*2048);
    asm volatile("cp.async.commit_group;");
  }

  #pragma unroll 1
  for (int c = 0; c < NCH; c++){
    __syncthreads();
    if (c + 2 < NCH){
      int cc = c + 2;
      unsigned sb = sbase + (cc % 3)*STG_B;
      CP16(sb + wOff,          gWh + cc*32);
      CP16(sb + 5120 + wOff,   gWl + cc*32);
      CP16(sb + 10240 + bOff,  gBh + (size_t)cc*2048);
      CP16(sb + 14848 + bOff,  gBl + (size_t)cc*2048);
      asm volatile("cp.async.commit_group;");
      asm volatile("cp.async.wait_group 2;");
    } else if (c + 1 < NCH){
      asm volatile("cp.async.wait_group 1;");
    } else {
      asm volatile("cp.async.wait_group 0;");
    }
    __syncthreads();
    const __nv_bfloat16* sWh = smem + (c % 3)*(STG_B/2);
    const __nv_bfloat16* sWl = sWh + 2560;
    const __nv_bfloat16* sBh = sWl + 2560;
    const __nv_bfloat16* sBl = sBh + 2304;
    #pragma unroll
    for (int s = 0; s < 2; s++){
      unsigned a0h = *(const unsigned*)&sWh[(jw+g  )*40 + s*16 + 2*qi];
      unsigned a1h = *(const unsigned*)&sWh[(jw+g+8)*40 + s*16 + 2*qi];
      unsigned a2h = *(const unsigned*)&sWh[(jw+g  )*40 + s*16 + 2*qi + 8];
      unsigned a3h = *(const unsigned*)&sWh[(jw+g+8)*40 + s*16 + 2*qi + 8];
      unsigned a0l = *(const unsigned*)&sWl[(jw+g  )*40 + s*16 + 2*qi];
      unsigned a1l = *(const unsigned*)&sWl[(jw+g+8)*40 + s*16 + 2*qi];
      unsigned a2l = *(const unsigned*)&sWl[(jw+g  )*40 + s*16 + 2*qi + 8];
      unsigned a3l = *(const unsigned*)&sWl[(jw+g+8)*40 + s*16 + 2*qi + 8];
      #pragma unroll
      for (int nt = 0; nt < 4; nt++){
        int n = bw + nt*8 + g;
        unsigned b0h = *(const unsigned*)&sBh[(s*8 + qi    )*144 + 2*n];
        unsigned b1h = *(const unsigned*)&sBh[(s*8 + 4 + qi)*144 + 2*n];
        unsigned b0l = *(const unsigned*)&sBl[(s*8 + qi    )*144 + 2*n];
        unsigned b1l = *(const unsigned*)&sBl[(s*8 + 4 + qi)*144 + 2*n];
        MMA_BF16(d[nt], a0h,a1h,a2h,a3h, b0h,b1h);
        MMA_BF16(d[nt], a0h,a1h,a2h,a3h, b0l,b1l);
        MMA_BF16(d[nt], a0l,a1l,a2l,a3l, b0h,b1h);
      }
    }
  }

  #pragma unroll
  for (int nt = 0; nt < 4; nt++){
    int b = bw + nt*8 + 2*qi;
    int jA = j0 + jw + g, jB = jA + 8;
    P[(size_t)(ks*64 + b    )*J + jA] = d[nt][0];
    P[(size_t)(ks*64 + b + 1)*J + jA] = d[nt][1];
    P[(size_t)(ks*64 + b    )*J + jB] = d[nt][2];
    P[(size_t)(ks*64 + b + 1)*J + jB] = d[nt][3];
  }
}

// ------------- point body (consumer in k_L) -------------
__device__ void point_body(int t, int m0, int b,
                           const float* __restrict__ aw,
                           const float* __restrict__ ab){
  int tid = threadIdx.x, warp = tid >> 5, lane = tid & 31;
  __shared__ float sg[1024], w1[224], wt[224], w2x[224], wb[64], wbx[64], red[16];
  __shared__ float s_ar;
  __shared__ int mEnd, m2End, bEnd, bxEnd;
  if (tid == 0){ mEnd = m0; m2End = m0; bEnd = 0; bxEnd = 0; }
  {
    float4 acc = *(const float4*)&g_bf[4*tid];
    #pragma unroll
    for (int ks = 0; ks < 8; ks++){
      float4 v = *(const float4*)&g_Gp[(size_t)(ks*64 + b)*1024 + 4*tid];
      acc.x += v.x; acc.y += v.y; acc.z += v.z; acc.w += v.w;
    }
    *(float4*)&sg[4*tid] = acc;
  }
  __syncthreads();
  {
    int h = tid;
    float gi = sg[h], gf = sg[256+h], gg = sg[512+h], go = sg[768+h];
    float c = g_c[b*HD + h];
    c = sigf(gf)*c + sigf(gi)*tanhf(gg);
    float hh = sigf(go)*tanhf(c);
    g_c[b*HD + h] = c;
    packAct(g_Aph, g_Apl, 768 + h, b, hh);
    float p0 = hh*aw[h], p1 = hh*aw[256+h];
    #pragma unroll
    for (int o = 16; o >= 1; o >>= 1){
      p0 += __shfl_xor_sync(0xffffffffu, p0, o);
      p1 += __shfl_xor_sync(0xffffffffu, p1, o);
    }
    if (lane == 0){ red[warp] = p0; red[8+warp] = p1; }
  }
  __syncthreads();
  if (tid == 0){
    float d0 = ab[0], d1 = ab[1];
    for (int w = 0; w < 8; w++){ d0 += red[w]; d1 += red[8+w]; }
    s_ar = sigf(10.f*(d0 - d1));
  }
  __syncthreads();
  float ar = s_ar, as = 1.f - ar;
  int idx = 191 - 2*t, idx2 = 190 - 2*t;
  if (warp == 0){
    scan_stack_pop(&g_s[b*MM], ar, w1, wt, w2x, &mEnd, &m2End);
    if (lane == 0){
      g_s[b*MM + idx] = ar;
      g_s[b*MM + idx2] = as;
      g_ar[b] = ar;
    }
  } else if (warp == 1){
    scan_buf_pop(&g_sb[b*SEQ], as, wb, wbx, &bEnd, &bxEnd);
  }
  __syncthreads();
  {
    int h = tid;
    int mm = max(mEnd, m2End);
    float r1 = 0.f, r2 = 0.f, x2 = 0.f;
    const float* Vb = g_V + (b*MM)*HD + h;
    for (int m = m0; m < mm; m++){
      float tw = wt[m], u2 = w2x[m];
      if (tw != 0.f || u2 != 0.f){
        float v = Vb[m*HD];
        r1 = fmaf(w1[m], v, r1);
        r2 = fmaf(tw - w1[m], v, r2);
        x2 = fmaf(u2, v, x2);
      }
    }
    packAct(g_A2ph, g_A2pl, h, b, r1);
    packAct(g_A2ph, g_A2pl, 256 + h, b, r2);
    g_r12[b*512 + h] = r1;
    g_r12[b*512 + 256 + h] = r2;
    packAct(g_Aph, g_Apl, 512 + h, b, x2);
    int bb = max(bEnd, bxEnd);
    float bv = 0.f, xb = 0.f;
    const float* Bb = g_B + (b*SEQ)*HD + h;
    for (int s2 = 0; s2 < bb; s2++){
      float w = wb[s2], wx = wbx[s2];
      if (w != 0.f || wx != 0.f){
        float v = Bb[s2*HD];
        bv = fmaf(w, v, bv);
        xb = fmaf(wx, v, xb);
      }
    }
    g_V[(b*MM + idx2)*HD + h] = bv;
    packAct(g_Aph, g_Apl, h, b, xb);
  }
}

// ------------- fused L: lstm GEMM (bids 0..127) + point (bids 128..191) -------------
__global__ void __launch_bounds__(256) k_L(int t, int m0,
                                           const float* __restrict__ aw,
                                           const float* __restrict__ ab){
  cudaGridDependencySynchronize();
  if (blockIdx.x < 128){
    gemm_cp<1024,1024,8>(g_Wfh, g_Wfl, g_Aph, g_Apl, g_Gp);
    prod_signal(&g_cntL);
  } else {
    cons_wait(&g_cntL, 128u*(unsigned)(t+1));
    point_body(t, m0, blockIdx.x - 128, aw, ab);
  }
}

// ------------- fused T: tree GEMM (bids 0..79) + epi (bids 80..143) -------------
__global__ void __launch_bounds__(256) k_T(int t){
  cudaGridDependencySynchronize();
  if (blockIdx.x < 80){
    gemm_cp<1280,512,4>(g_Wth, g_Wtl, g_A2ph, g_A2pl, g_Tp);
    prod_signal(&g_cntT);
  } else {
    cons_wait(&g_cntT, 80u*(unsigned)(t+1));
    int b = blockIdx.x - 80, tid = threadIdx.x;
    __shared__ float stg[1280];
    for (int j4 = tid; j4 < 320; j4 += 256){
      float4 acc = *(const float4*)&g_bt[4*j4];
      #pragma unroll
      for (int ks = 0; ks < 4; ks++){
        float4 v = *(const float4*)&g_Tp[(size_t)(ks*64 + b)*1280 + 4*j4];
        acc.x += v.x; acc.y += v.y; acc.z += v.z; acc.w += v.w;
      }
      *(float4*)&stg[4*j4] = acc;
    }
    __syncthreads();
    int h = tid;
    float ta = stg[h], ti = stg[256+h], f1 = stg[512+h], f2 = stg[768+h], to = stg[1024+h];
    float r1 = g_r12[b*512 + h], r2 = g_r12[b*512 + 256 + h];
    float ct = tanhf(ta)*sigf(ti) + sigf(f1)*r1 + sigf(f2)*r2;
    float ht = sigf(to)*tanhf(ct);
    int idx = 191 - 2*t, idx2 = 190 - 2*t;
    g_V[(b*MM + idx)*HD + h] = ht;
    float bv = g_V[(b*MM + idx2)*HD + h];
    float ar = g_ar[b], as = 1.f - ar;
    float x1 = as*bv + ar*ht;
    packAct(g_Aph, g_Apl, 256 + h, b, x1);
  }
}

// ------------- initial read (t = -1): alpha=1 buffer read -> xb -------------
__global__ void __launch_bounds__(256) k_epi0(){
  int b = blockIdx.x, tid = threadIdx.x, warp = tid >> 5;
  __shared__ float wbs[64];
  __shared__ int bEnd;
  if (tid == 0) bEnd = 0;
  cudaGridDependencySynchronize();
  __syncthreads();
  if (warp == 0) scan_buf(&g_sb[b*SEQ], 1.f, wbs, &bEnd);
  __syncthreads();
  int h = tid, be = bEnd;
  float xb = 0.f;
  const float* Bb = g_B + (b*SEQ)*HD + h;
  for (int s2 = 0; s2 < be; s2++){
    float w = wbs[s2];
    if (w != 0.f) xb = fmaf(w, Bb[s2*HD], xb);
  }
  packAct(g_Aph, g_Apl, h, b, xb);
}

// ------------- MLP tail GEMMs -------------
__global__ void __launch_bounds__(256) k_mlp0g(){
  cudaGridDependencySynchronize();
  gemm_cp<1024,256,2>(g_Wm0h, g_Wm0l, g_Aph + 128*128, g_Apl + 128*128, g_Tp);
}
__global__ void __launch_bounds__(256) k_mlp1g(){
  cudaGridDependencySynchronize();
  gemm_cp<1024,1024,8>(g_Wm1h, g_Wm1l, g_Aph, g_Apl, g_Gp);
}

__global__ void __launch_bounds__(256) k_r0(const float* __restrict__ l0b){
  cudaGridDependencySynchronize();
  int b = blockIdx.x, tid = threadIdx.x;
  float4 acc = *(const float4*)&l0b[4*tid];
  #pragma unroll
  for (int ks = 0; ks < 2; ks++){
    float4 v = *(const float4*)&g_Tp[(size_t)(ks*64 + b)*1024 + 4*tid];
    acc.x += v.x; acc.y += v.y; acc.z += v.z; acc.w += v.w;
  }
  acc.x = fmaxf(acc.x, 0.f);
  acc.y = fmaxf(acc.y, 0.f);
  acc.z = fmaxf(acc.z, 0.f);
  acc.w = fmaxf(acc.w, 0.f);
  packAct(g_Aph, g_Apl, 4*tid    , b, acc.x);
  packAct(g_Aph, g_Apl, 4*tid + 1, b, acc.y);
  packAct(g_Aph, g_Apl, 4*tid + 2, b, acc.z);
  packAct(g_Aph, g_Apl, 4*tid + 3, b, acc.w);
}

__global__ void __launch_bounds__(256) k_r1(const float* __restrict__ l1b){
  cudaGridDependencySynchronize();
  int b = blockIdx.x, tid = threadIdx.x;
  float4 acc = *(const float4*)&l1b[4*tid];
  #pragma unroll
  for (int ks = 0; ks < 8; ks++){
    float4 v = *(const float4*)&g_Gp[(size_t)(ks*64 + b)*1024 + 4*tid];
    acc.x += v.x; acc.y += v.y; acc.z += v.z; acc.w += v.w;
  }
  acc.x = fmaxf(acc.x, 0.f); acc.y = fmaxf(acc.y, 0.f);
  acc.z = fmaxf(acc.z, 0.f); acc.w = fmaxf(acc.w, 0.f);
  *(float4*)&g_y1[b*1024 + 4*tid] = acc;
}

__global__ void __launch_bounds__(256) k_mlp2(const float* __restrict__ l2w,
                                              const float* __restrict__ l2b,
                                              float* __restrict__ out){
  cudaGridDependencySynchronize();
  int b = blockIdx.x, tid = threadIdx.x, warp = tid >> 5, lane = tid & 31;
  __shared__ float red[8];
  for (int c = 0; c < 3; c++){
    float p = 0.f;
    for (int k = tid; k < 1024; k += 256)
      p = fmaf(g_y1[b*1024 + k], l2w[c*1024 + k], p);
    #pragma unroll
    for (int o = 16; o >= 1; o >>= 1) p += __shfl_xor_sync(0xffffffffu, p, o);
    if (lane == 0) red[warp] = p;
    __syncthreads();
    if (tid == 0){
      float s = l2b[c];
      for (int w = 0; w < 8; w++) s += red[w];
      out[b*3 + c] = s;
    }
    __syncthreads();
  }
}

// ------------- PDL launch helper -------------
template <typename F, typename... Args>
static inline void launchP(F f, int grid, int block, size_t smem, Args... args){
  cudaLaunchConfig_t cfg;
  memset(&cfg, 0, sizeof(cfg));
  cfg.gridDim = dim3(grid, 1, 1);
  cfg.blockDim = dim3(block, 1, 1);
  cfg.dynamicSmemBytes = smem;
  cfg.stream = 0;
  cudaLaunchAttribute at[1];
  at[0].id = cudaLaunchAttributeProgrammaticStreamSerialization;
  at[0].val.programmaticStreamSerializationAllowed = 1;
  cfg.attrs = at;
  cfg.numAttrs = 1;
  cudaLaunchKernelEx(&cfg, f, args...);
}

// ------------- launch -------------
extern "C" void kernel_launch(void* const* d_in, const int* in_sizes, int n_in,
                              void* d_out, int out_size){
  const void*  x   = d_in[0];
  const float* emb = (const float*)d_in[1];
  const float* wih = (const float*)d_in[2];
  const float* whh = (const float*)d_in[3];
  const float* bih = (const float*)d_in[4];
  const float* bhh = (const float*)d_in[5];
  const float* aw  = (const float*)d_in[6];
  const float* ab  = (const float*)d_in[7];
  const float* lw  = (const float*)d_in[8];
  const float* lb  = (const float*)d_in[9];
  const float* rw  = (const float*)d_in[10];
  const float* rb  = (const float*)d_in[11];
  const float* l0w = (const float*)d_in[12];
  const float* l0b = (const float*)d_in[13];
  const float* l1w = (const float*)d_in[14];
  const float* l1b = (const float*)d_in[15];
  const float* l2w = (const float*)d_in[16];
  const float* l2b = (const float*)d_in[17];
  float* out = (float*)d_out;

  const int SMEMB = 3*STG_B;   // 58368 bytes
  static int attr_done = 0;
  if (!attr_done){
    cudaFuncSetAttribute(k_L,     cudaFuncAttributeMaxDynamicSharedMemorySize, SMEMB);
    cudaFuncSetAttribute(k_T,     cudaFuncAttributeMaxDynamicSharedMemorySize, SMEMB);
    cudaFuncSetAttribute(k_mlp0g, cudaFuncAttributeMaxDynamicSharedMemorySize, SMEMB);
    cudaFuncSetAttribute(k_mlp1g, cudaFuncAttributeMaxDynamicSharedMemorySize, SMEMB);
    attr_done = 1;
  }

  k_tok<<<1, 256>>>(x);
  launchP(k_prep, 512, 256, 0, x, emb, wih, whh, bih, bhh, lw, lb, rw, rb, l0w, l1w);
  launchP(k_epi0, 64, 256, 0);
  for (int t = 0; t < TSTEPS; t++){
    int m0p = 192 - 2*t; if (m0p < 0) m0p = 0;
    launchP(k_L, 192, 256, (size_t)SMEMB, t, m0p, aw, ab);
    launchP(k_T, 144, 256, (size_t)SMEMB, t);
  }
  launchP(k_mlp0g, 32, 256, (size_t)SMEMB);
  launchP(k_r0, 64, 256, 0, l0b);
  launchP(k_mlp1g, 128, 256, (size_t)SMEMB);
  launchP(k_r1, 64, 256, 0, l1b);
  launchP(k_mlp2, 64, 256, 0, l2w, l2b, out);
}

// round 17
// speedup vs baseline: 1.1847x; 1.1847x over previous
#include <cuda_runtime.h>
#include <cuda_bf16.h>

#define BN 64
#define SEQ 48
#define HD 256
#define MM 193
#define TSTEPS 96

// ------------- device scratch -------------
__device__ float g_B [BN*SEQ*HD];
__device__ float g_sb[BN*SEQ];
__device__ float g_V [BN*MM*HD];
__device__ float g_s [BN*MM];
__device__ float g_c [BN*HD];
__device__ float g_ar[BN];
__device__ __align__(16) __nv_bfloat16 g_Wfh[1024*1024], g_Wfl[1024*1024];
__device__ __align__(16) __nv_bfloat16 g_Wth[1280*512],  g_Wtl[1280*512];
__device__ __align__(16) __nv_bfloat16 g_Wm0h[1024*256], g_Wm0l[1024*256];
__device__ __align__(16) __nv_bfloat16 g_Wm1h[1024*1024], g_Wm1l[1024*1024];
__device__ __align__(16) __nv_bfloat16 g_Aph [512*128], g_Apl [512*128];
__device__ __align__(16) __nv_bfloat16 g_A2ph[256*128], g_A2pl[256*128];
__device__ float g_r12[BN*512];
__device__ float g_bf[1024];
__device__ float g_bt[1280];
__device__ float g_Gp[8*BN*1024];
__device__ float g_Tp[4*BN*1280];
__device__ float g_y1[BN*1024];
__device__ int   g_is64;

__device__ __forceinline__ float sigf(float x){ return 1.f/(1.f+expf(-x)); }

__device__ __forceinline__ void packAct(__nv_bfloat16* Ah, __nv_bfloat16* Al,
                                        int k, int b, float v){
  __nv_bfloat16 hi = __float2bfloat16(v);
  float lo = v - __bfloat162float(hi);
  int idx = (k >> 1)*128 + 2*b + (k & 1);
  Ah[idx] = hi;
  Al[idx] = __float2bfloat16(lo);
}

#define MMA_BF16(D, A0,A1,A2,A3, B0,B1) \
  asm volatile("mma.sync.aligned.m16n8k16.row.col.f32.bf16.bf16.f32 " \
      "{%0,%1,%2,%3}, {%4,%5,%6,%7}, {%8,%9}, {%0,%1,%2,%3};" \
      : "+f"(D[0]),"+f"(D[1]),"+f"(D[2]),"+f"(D[3]) \
      : "r"(A0),"r"(A1),"r"(A2),"r"(A3),"r"(B0),"r"(B1))

#define CP16(dst, src) \
  asm volatile("cp.async.cg.shared.global [%0], [%1], 16;" :: "r"(dst), "l"(src))

// ------------- warp scans -------------
__device__ __forceinline__ void scan_stack_pop(float* srow, float a,
                                               float* w1, float* wt, float* w2x,
                                               int* mEnd, int* m2End){
  int lane = threadIdx.x & 31;
  float run = 0.f;
  #pragma unroll
  for (int c = 0; c < 7; c++){
    int m = c*32 + lane;
    float sv = (m < MM) ? srow[m] : 0.f;
    float v = sv;
    #pragma unroll
    for (int o = 1; o < 32; o <<= 1){
      float n = __shfl_up_sync(0xffffffffu, v, o);
      if (lane >= o) v += n;
    }
    float Pm = run + v, Pp = Pm - sv;
    float u1 = fminf(Pm, a) - fminf(Pp, a);
    float ut = fminf(Pm, 1.f + a) - fminf(Pp, 1.f + a);
    float Qm = fmaxf(0.f, Pm - (1.f + a));
    float Qp = fmaxf(0.f, Pp - (1.f + a));
    float u2 = fminf(Qm, 1.f) - fminf(Qp, 1.f);
    if (m < MM){
      w1[m] = u1; wt[m] = ut; w2x[m] = u2;
      srow[m] = sv - ut;
      if (ut > 0.f) atomicMax(mEnd, m + 1);
      if (u2 > 0.f) atomicMax(m2End, m + 1);
    }
    run += __shfl_sync(0xffffffffu, v, 31);
  }
  __syncwarp();
}

__device__ __forceinline__ void scan_buf_pop(float* srow, float a,
                                             float* wb, float* wbx,
                                             int* bEnd, int* bxEnd){
  int lane = threadIdx.x & 31;
  float run = 0.f;
  #pragma unroll
  for (int c = 0; c < 2; c++){
    int m = c*32 + lane;
    float sv = (m < SEQ) ? srow[m] : 0.f;
    float v = sv;
    #pragma unroll
    for (int o = 1; o < 32; o <<= 1){
      float n = __shfl_up_sync(0xffffffffu, v, o);
      if (lane >= o) v += n;
    }
    float Pm = run + v, Pp = Pm - sv;
    float w = fminf(Pm, a) - fminf(Pp, a);
    float Qm = fmaxf(0.f, Pm - a);
    float Qp = fmaxf(0.f, Pp - a);
    float wx = fminf(Qm, 1.f) - fminf(Qp, 1.f);
    if (m < SEQ){
      wb[m] = w; wbx[m] = wx;
      srow[m] = sv - w;
      if (w  > 0.f) atomicMax(bEnd,  m + 1);
      if (wx > 0.f) atomicMax(bxEnd, m + 1);
    }
    run += __shfl_sync(0xffffffffu, v, 31);
  }
  __syncwarp();
}

__device__ __forceinline__ void scan_buf(float* srow, float a, float* wb, int* bEnd){
  int lane = threadIdx.x & 31;
  float run = 0.f;
  #pragma unroll
  for (int c = 0; c < 2; c++){
    int m = c*32 + lane;
    float sv = (m < SEQ) ? srow[m] : 0.f;
    float v = sv;
    #pragma unroll
    for (int o = 1; o < 32; o <<= 1){
      float n = __shfl_up_sync(0xffffffffu, v, o);
      if (lane >= o) v += n;
    }
    float Pm = run + v, Pp = Pm - sv;
    float w = fminf(Pm, a) - fminf(Pp, a);
    if (m < SEQ){
      wb[m] = w;
      if (w > 0.f) atomicMax(bEnd, m + 1);
    }
    run += __shfl_sync(0xffffffffu, v, 31);
  }
  __syncwarp();
}

// ------------- token dtype detect -------------
__global__ void k_tok(const void* x){
  __shared__ int ok;
  if (threadIdx.x == 0) ok = 1;
  __syncthreads();
  const long long* xl = (const long long*)x;
  int bad = 0;
  for (int i = threadIdx.x; i < (BN*SEQ)/2; i += 256){
    long long v = xl[i];
    if (v < 0 || v >= 50257) bad = 1;
  }
  if (bad) atomicAnd(&ok, 0);
  __syncthreads();
  if (threadIdx.x == 0) g_is64 = ok;
}

// ------------- prep -------------
__global__ void k_prep(const void* x, const float* emb,
                       const float* wih, const float* whh,
                       const float* bih, const float* bhh,
                       const float* lw, const float* lb,
                       const float* rw, const float* rb,
                       const float* l0w, const float* l1w){
  cudaGridDependencySynchronize();
  int gid = blockIdx.x*blockDim.x + threadIdx.x;
  int gsz = gridDim.x*blockDim.x;
  int is64 = g_is64;
  const long long* xl = (const long long*)x;
  const int* xi = (const int*)x;
  for (int i = gid; i < BN*SEQ; i += gsz){
    long long tok = is64 ? xl[i] : (long long)xi[i];
    g_sb[i] = (tok > 0) ? 1.f : 0.f;
  }
  for (int i = gid; i < BN*SEQ*HD; i += gsz){
    int row = i >> 8;
    long long tok = is64 ? xl[row] : (long long)xi[row];
    g_B[i] = emb[(size_t)tok*HD + (i & 255)];
  }
  for (int i = gid; i < 1024*1024; i += gsz){
    int j = i >> 10, k = i & 1023;
    float wv = (k < 768) ? wih[j*768 + k] : whh[j*256 + (k-768)];
    __nv_bfloat16 hi = __float2bfloat16(wv);
    g_Wfh[i] = hi;
    g_Wfl[i] = __float2bfloat16(wv - __bfloat162float(hi));
  }
  for (int i = gid; i < 1280*512; i += gsz){
    int j = i >> 9, k = i & 511;
    float wv = (k < 256) ? lw[j*256 + k] : rw[j*256 + (k-256)];
    __nv_bfloat16 hi = __float2bfloat16(wv);
    g_Wth[i] = hi;
    g_Wtl[i] = __float2bfloat16(wv - __bfloat162float(hi));
  }
  for (int i = gid; i < 1024*256; i += gsz){
    float wv = l0w[i];
    __nv_bfloat16 hi = __float2bfloat16(wv);
    g_Wm0h[i] = hi;
    g_Wm0l[i] = __float2bfloat16(wv - __bfloat162float(hi));
  }
  for (int i = gid; i < 1024*1024; i += gsz){
    float wv = l1w[i];
    __nv_bfloat16 hi = __float2bfloat16(wv);
    g_Wm1h[i] = hi;
    g_Wm1l[i] = __float2bfloat16(wv - __bfloat162float(hi));
  }
  for (int i = gid; i < 1024; i += gsz) g_bf[i] = bih[i] + bhh[i];
  for (int i = gid; i < 1280; i += gsz) g_bt[i] = lb[i] + rb[i];
  for (int i = gid; i < BN*MM*HD; i += gsz) g_V[i] = 0.f;
  for (int i = gid; i < BN*MM; i += gsz) g_s[i] = 0.f;
  for (int i = gid; i < BN*HD; i += gsz) g_c[i] = 0.f;
  __nv_bfloat16 z = __float2bfloat16(0.f);
  for (int i = gid; i < 512*128; i += gsz){ g_Aph[i] = z; g_Apl[i] = z; }
  for (int i = gid; i < 256*128; i += gsz){ g_A2ph[i] = z; g_A2pl[i] = z; }
}

// ------------- cp.async 3-stage bf16 MMA GEMM (2-split compensated) -------------
// PDL prologue-overlap: weight cp.asyncs for stages 0,1 are issued BEFORE
// cudaGridDependencySynchronize() (weights are step-invariant, written only by
// k_prep); activation (B) cp.asyncs wait for the predecessor. Group order per
// thread: G0=W0, G1=W1, G2=B0, G3=B1, then combined W+B groups — the
// wait_group 2/1/0 schedule guarantees chunk c's W and B are resident.
#define STG_B 19456
template<int J, int K, int NKS>
__device__ __forceinline__ void gemm_cp(const __nv_bfloat16* __restrict__ Wh,
                                        const __nv_bfloat16* __restrict__ Wl,
                                        const __nv_bfloat16* __restrict__ Bh,
                                        const __nv_bfloat16* __restrict__ Bl,
                                        float* __restrict__ P){
  constexpr int KSL = K / NKS;
  constexpr int NCH = KSL / 32;
  extern __shared__ __nv_bfloat16 smem[];
  const int jt = blockIdx.x / NKS, ks = blockIdx.x % NKS;
  const int j0 = jt*64, k0 = ks*KSL;
  const int tid = threadIdx.x;
  const int w = tid >> 5, l = tid & 31, g = l >> 2, qi = l & 3;
  const int jw = (w & 3)*16, bw = (w >> 2)*32;
  const int jrow = tid >> 2, kq = tid & 3;
  const int brow = tid >> 4, bo = tid & 15;

  const __nv_bfloat16* gWh = Wh + (size_t)(j0 + jrow)*K + k0 + kq*8;
  const __nv_bfloat16* gWl = Wl + (size_t)(j0 + jrow)*K + k0 + kq*8;
  const __nv_bfloat16* gBh = Bh + (size_t)(k0/2 + brow)*128 + bo*8;
  const __nv_bfloat16* gBl = Bl + (size_t)(k0/2 + brow)*128 + bo*8;

  const unsigned sbase = (unsigned)__cvta_generic_to_shared(smem);
  const unsigned wOff = (jrow*40 + kq*8)*2;
  const unsigned bOff = (brow*144 + bo*8)*2;

  float d[4][4];
  #pragma unroll
  for (int i = 0; i < 4; i++)
    #pragma unroll
    for (int j = 0; j < 4; j++) d[i][j] = 0.f;

  // --- pre-sync: weight prefetch for stages 0,1 (groups G0, G1) ---
  #pragma unroll
  for (int cc = 0; cc < 2; cc++){
    unsigned sb = sbase + cc*STG_B;
    CP16(sb + wOff,        gWh + cc*32);
    CP16(sb + 5120 + wOff, gWl + cc*32);
    asm volatile("cp.async.commit_group;");
  }

  cudaGridDependencySynchronize();

  // --- post-sync: activation loads for stages 0,1 (groups G2, G3) ---
  #pragma unroll
  for (int cc = 0; cc < 2; cc++){
    unsigned sb = sbase + cc*STG_B;
    CP16(sb + 10240 + bOff, gBh + (size_t)cc*2048);
    CP16(sb + 14848 + bOff, gBl + (size_t)cc*2048);
    asm volatile("cp.async.commit_group;");
  }

  #pragma unroll 1
  for (int c = 0; c < NCH; c++){
    __syncthreads();
    if (c + 2 < NCH){
      int cc = c + 2;
      unsigned sb = sbase + (cc % 3)*STG_B;
      CP16(sb + wOff,          gWh + cc*32);
      CP16(sb + 5120 + wOff,   gWl + cc*32);
      CP16(sb + 10240 + bOff,  gBh + (size_t)cc*2048);
      CP16(sb + 14848 + bOff,  gBl + (size_t)cc*2048);
      asm volatile("cp.async.commit_group;");
      asm volatile("cp.async.wait_group 2;");
    } else if (c + 1 < NCH){
      asm volatile("cp.async.wait_group 1;");
    } else {
      asm volatile("cp.async.wait_group 0;");
    }
    __syncthreads();
    const __nv_bfloat16* sWh = smem + (c % 3)*(STG_B/2);
    const __nv_bfloat16* sWl = sWh + 2560;
    const __nv_bfloat16* sBh = sWl + 2560;
    const __nv_bfloat16* sBl = sBh + 2304;
    #pragma unroll
    for (int s = 0; s < 2; s++){
      unsigned a0h = *(const unsigned*)&sWh[(jw+g  )*40 + s*16 + 2*qi];
      unsigned a1h = *(const unsigned*)&sWh[(jw+g+8)*40 + s*16 + 2*qi];
      unsigned a2h = *(const unsigned*)&sWh[(jw+g  )*40 + s*16 + 2*qi + 8];
      unsigned a3h = *(const unsigned*)&sWh[(jw+g+8)*40 + s*16 + 2*qi + 8];
      unsigned a0l = *(const unsigned*)&sWl[(jw+g  )*40 + s*16 + 2*qi];
      unsigned a1l = *(const unsigned*)&sWl[(jw+g+8)*40 + s*16 + 2*qi];
      unsigned a2l = *(const unsigned*)&sWl[(jw+g  )*40 + s*16 + 2*qi + 8];
      unsigned a3l = *(const unsigned*)&sWl[(jw+g+8)*40 + s*16 + 2*qi + 8];
      #pragma unroll
      for (int nt = 0; nt < 4; nt++){
        int n = bw + nt*8 + g;
        unsigned b0h = *(const unsigned*)&sBh[(s*8 + qi    )*144 + 2*n];
        unsigned b1h = *(const unsigned*)&sBh[(s*8 + 4 + qi)*144 + 2*n];
        unsigned b0l = *(const unsigned*)&sBl[(s*8 + qi    )*144 + 2*n];
        unsigned b1l = *(const unsigned*)&sBl[(s*8 + 4 + qi)*144 + 2*n];
        MMA_BF16(d[nt], a0h,a1h,a2h,a3h, b0h,b1h);
        MMA_BF16(d[nt], a0h,a1h,a2h,a3h, b0l,b1l);
        MMA_BF16(d[nt], a0l,a1l,a2l,a3l, b0h,b1h);
      }
    }
  }

  #pragma unroll
  for (int nt = 0; nt < 4; nt++){
    int b = bw + nt*8 + 2*qi;
    int jA = j0 + jw + g, jB = jA + 8;
    P[(size_t)(ks*64 + b    )*J + jA] = d[nt][0];
    P[(size_t)(ks*64 + b + 1)*J + jA] = d[nt][1];
    P[(size_t)(ks*64 + b    )*J + jB] = d[nt][2];
    P[(size_t)(ks*64 + b + 1)*J + jB] = d[nt][3];
  }
}

__global__ void __launch_bounds__(256) k_lstm(){
  gemm_cp<1024,1024,8>(g_Wfh, g_Wfl, g_Aph, g_Apl, g_Gp);
}
__global__ void __launch_bounds__(256) k_tree(){
  gemm_cp<1280,512,4>(g_Wth, g_Wtl, g_A2ph, g_A2pl, g_Tp);
}
__global__ void __launch_bounds__(256) k_mlp0g(){
  gemm_cp<1024,256,2>(g_Wm0h, g_Wm0l, g_Aph + 128*128, g_Apl + 128*128, g_Tp);
}
__global__ void __launch_bounds__(256) k_mlp1g(){
  gemm_cp<1024,1024,8>(g_Wm1h, g_Wm1l, g_Aph, g_Apl, g_Gp);
}

// ------------- pointwise: gates, alphas, pops, reads + next-step xb/x2 -------------
__global__ void __launch_bounds__(256) k_point(int t, int m0, const float* __restrict__ aw,
                                               const float* __restrict__ ab){
  int b = blockIdx.x, tid = threadIdx.x, warp = tid >> 5, lane = tid & 31;
  __shared__ float sg[1024], w1[224], wt[224], w2x[224], wb[64], wbx[64], red[16];
  __shared__ float s_ar;
  __shared__ int mEnd, m2End, bEnd, bxEnd;
  if (tid == 0){ mEnd = m0; m2End = m0; bEnd = 0; bxEnd = 0; }
  cudaGridDependencySynchronize();
  {
    float4 acc = *(const float4*)&g_bf[4*tid];
    #pragma unroll
    for (int ks = 0; ks < 8; ks++){
      float4 v = *(const float4*)&g_Gp[(size_t)(ks*64 + b)*1024 + 4*tid];
      acc.x += v.x; acc.y += v.y; acc.z += v.z; acc.w += v.w;
    }
    *(float4*)&sg[4*tid] = acc;
  }
  __syncthreads();
  {
    int h = tid;
    float gi = sg[h], gf = sg[256+h], gg = sg[512+h], go = sg[768+h];
    float c = g_c[b*HD + h];
    c = sigf(gf)*c + sigf(gi)*tanhf(gg);
    float hh = sigf(go)*tanhf(c);
    g_c[b*HD + h] = c;
    packAct(g_Aph, g_Apl, 768 + h, b, hh);
    float p0 = hh*aw[h], p1 = hh*aw[256+h];
    #pragma unroll
    for (int o = 16; o >= 1; o >>= 1){
      p0 += __shfl_xor_sync(0xffffffffu, p0, o);
      p1 += __shfl_xor_sync(0xffffffffu, p1, o);
    }
    if (lane == 0){ red[warp] = p0; red[8+warp] = p1; }
  }
  __syncthreads();
  if (tid == 0){
    float d0 = ab[0], d1 = ab[1];
    for (int w = 0; w < 8; w++){ d0 += red[w]; d1 += red[8+w]; }
    s_ar = sigf(10.f*(d0 - d1));
  }
  __syncthreads();
  float ar = s_ar, as = 1.f - ar;
  int idx = 191 - 2*t, idx2 = 190 - 2*t;
  if (warp == 0){
    scan_stack_pop(&g_s[b*MM], ar, w1, wt, w2x, &mEnd, &m2End);
    if (lane == 0){
      g_s[b*MM + idx] = ar;
      g_s[b*MM + idx2] = as;
      g_ar[b] = ar;
    }
  } else if (warp == 1){
    scan_buf_pop(&g_sb[b*SEQ], as, wb, wbx, &bEnd, &bxEnd);
  }
  __syncthreads();
  {
    int h = tid;
    int mm = max(mEnd, m2End);
    float r1 = 0.f, r2 = 0.f, x2 = 0.f;
    const float* Vb = g_V + (b*MM)*HD + h;
    for (int m = m0; m < mm; m++){
      float tw = wt[m], u2 = w2x[m];
      if (tw != 0.f || u2 != 0.f){
        float v = Vb[m*HD];
        r1 = fmaf(w1[m], v, r1);
        r2 = fmaf(tw - w1[m], v, r2);
        x2 = fmaf(u2, v, x2);
      }
    }
    packAct(g_A2ph, g_A2pl, h, b, r1);
    packAct(g_A2ph, g_A2pl, 256 + h, b, r2);
    g_r12[b*512 + h] = r1;
    g_r12[b*512 + 256 + h] = r2;
    packAct(g_Aph, g_Apl, 512 + h, b, x2);
    int bb = max(bEnd, bxEnd);
    float bv = 0.f, xb = 0.f;
    const float* Bb = g_B + (b*SEQ)*HD + h;
    for (int s2 = 0; s2 < bb; s2++){
      float w = wb[s2], wx = wbx[s2];
      if (w != 0.f || wx != 0.f){
        float v = Bb[s2*HD];
        bv = fmaf(w, v, bv);
        xb = fmaf(wx, v, xb);
      }
    }
    g_V[(b*MM + idx2)*HD + h] = bv;
    packAct(g_Aph, g_Apl, h, b, xb);
  }
}

// ------------- epilogue: tree cell + x1 identity (no scans) -------------
__global__ void __launch_bounds__(256) k_epi(int t){
  int b = blockIdx.x, tid = threadIdx.x, warp = tid >> 5;
  __shared__ float stg[1280];
  __shared__ float wbs[64];
  __shared__ int bEnd;
  if (tid == 0) bEnd = 0;
  cudaGridDependencySynchronize();
  if (t >= 0){
    for (int j4 = tid; j4 < 320; j4 += 256){
      float4 acc = *(const float4*)&g_bt[4*j4];
      #pragma unroll
      for (int ks = 0; ks < 4; ks++){
        float4 v = *(const float4*)&g_Tp[(size_t)(ks*64 + b)*1280 + 4*j4];
        acc.x += v.x; acc.y += v.y; acc.z += v.z; acc.w += v.w;
      }
      *(float4*)&stg[4*j4] = acc;
    }
    __syncthreads();
    int h = tid;
    float ta = stg[h], ti = stg[256+h], f1 = stg[512+h], f2 = stg[768+h], to = stg[1024+h];
    float r1 = g_r12[b*512 + h], r2 = g_r12[b*512 + 256 + h];
    float ct = tanhf(ta)*sigf(ti) + sigf(f1)*r1 + sigf(f2)*r2;
    float ht = sigf(to)*tanhf(ct);
    int idx = 191 - 2*t, idx2 = 190 - 2*t;
    g_V[(b*MM + idx)*HD + h] = ht;
    float bv = g_V[(b*MM + idx2)*HD + h];
    float ar = g_ar[b], as = 1.f - ar;
    float x1 = as*bv + ar*ht;
    packAct(g_Aph, g_Apl, 256 + h, b, x1);
  } else {
    __syncthreads();
    if (warp == 0) scan_buf(&g_sb[b*SEQ], 1.f, wbs, &bEnd);
    __syncthreads();
    int h = tid, be = bEnd;
    float xb = 0.f;
    const float* Bb = g_B + (b*SEQ)*HD + h;
    for (int s2 = 0; s2 < be; s2++){
      float w = wbs[s2];
      if (w != 0.f) xb = fmaf(w, Bb[s2*HD], xb);
    }
    packAct(g_Aph, g_Apl, h, b, xb);
  }
}

// ------------- MLP reduce/relu/pack kernels -------------
__global__ void __launch_bounds__(256) k_r0(const float* __restrict__ l0b){
  cudaGridDependencySynchronize();
  int b = blockIdx.x, tid = threadIdx.x;
  float4 acc = *(const float4*)&l0b[4*tid];
  #pragma unroll
  for (int ks = 0; ks < 2; ks++){
    float4 v = *(const float4*)&g_Tp[(size_t)(ks*64 + b)*1024 + 4*tid];
    acc.x += v.x; acc.y += v.y; acc.z += v.z; acc.w += v.w;
  }
  acc.x = fmaxf(acc.x, 0.f);
  acc.y = fmaxf(acc.y, 0.f);
  acc.z = fmaxf(acc.z, 0.f);
  acc.w = fmaxf(acc.w, 0.f);
  packAct(g_Aph, g_Apl, 4*tid    , b, acc.x);
  packAct(g_Aph, g_Apl, 4*tid + 1, b, acc.y);
  packAct(g_Aph, g_Apl, 4*tid + 2, b, acc.z);
  packAct(g_Aph, g_Apl, 4*tid + 3, b, acc.w);
}

__global__ void __launch_bounds__(256) k_r1(const float* __restrict__ l1b){
  cudaGridDependencySynchronize();
  int b = blockIdx.x, tid = threadIdx.x;
  float4 acc = *(const float4*)&l1b[4*tid];
  #pragma unroll
  for (int ks = 0; ks < 8; ks++){
    float4 v = *(const float4*)&g_Gp[(size_t)(ks*64 + b)*1024 + 4*tid];
    acc.x += v.x; acc.y += v.y; acc.z += v.z; acc.w += v.w;
  }
  acc.x = fmaxf(acc.x, 0.f); acc.y = fmaxf(acc.y, 0.f);
  acc.z = fmaxf(acc.z, 0.f); acc.w = fmaxf(acc.w, 0.f);
  *(float4*)&g_y1[b*1024 + 4*tid] = acc;
}

__global__ void __launch_bounds__(256) k_mlp2(const float* __restrict__ l2w,
                                              const float* __restrict__ l2b,
                                              float* __restrict__ out){
  cudaGridDependencySynchronize();
  int b = blockIdx.x, tid = threadIdx.x, warp = tid >> 5, lane = tid & 31;
  __shared__ float red[8];
  for (int c = 0; c < 3; c++){
    float p = 0.f;
    for (int k = tid; k < 1024; k += 256)
      p = fmaf(g_y1[b*1024 + k], l2w[c*1024 + k], p);
    #pragma unroll
    for (int o = 16; o >= 1; o >>= 1) p += __shfl_xor_sync(0xffffffffu, p, o);
    if (lane == 0) red[warp] = p;
    __syncthreads();
    if (tid == 0){
      float s = l2b[c];
      for (int w = 0; w < 8; w++) s += red[w];
      out[b*3 + c] = s;
    }
    __syncthreads();
  }
}

// ------------- PDL launch helper -------------
template <typename F, typename... Args>
static inline void launchP(F f, int grid, int block, size_t smem, Args... args){
  cudaLaunchConfig_t cfg;
  memset(&cfg, 0, sizeof(cfg));
  cfg.gridDim = dim3(grid, 1, 1);
  cfg.blockDim = dim3(block, 1, 1);
  cfg.dynamicSmemBytes = smem;
  cfg.stream = 0;
  cudaLaunchAttribute at[1];
  at[0].id = cudaLaunchAttributeProgrammaticStreamSerialization;
  at[0].val.programmaticStreamSerializationAllowed = 1;
  cfg.attrs = at;
  cfg.numAttrs = 1;
  cudaLaunchKernelEx(&cfg, f, args...);
}

// ------------- launch -------------
extern "C" void kernel_launch(void* const* d_in, const int* in_sizes, int n_in,
                              void* d_out, int out_size){
  const void*  x   = d_in[0];
  const float* emb = (const float*)d_in[1];
  const float* wih = (const float*)d_in[2];
  const float* whh = (const float*)d_in[3];
  const float* bih = (const float*)d_in[4];
  const float* bhh = (const float*)d_in[5];
  const float* aw  = (const float*)d_in[6];
  const float* ab  = (const float*)d_in[7];
  const float* lw  = (const float*)d_in[8];
  const float* lb  = (const float*)d_in[9];
  const float* rw  = (const float*)d_in[10];
  const float* rb  = (const float*)d_in[11];
  const float* l0w = (const float*)d_in[12];
  const float* l0b = (const float*)d_in[13];
  const float* l1w = (const float*)d_in[14];
  const float* l1b = (const float*)d_in[15];
  const float* l2w = (const float*)d_in[16];
  const float* l2b = (const float*)d_in[17];
  float* out = (float*)d_out;

  const int SMEMB = 3*STG_B;   // 58368 bytes
  static int attr_done = 0;
  if (!attr_done){
    cudaFuncSetAttribute(k_lstm,  cudaFuncAttributeMaxDynamicSharedMemorySize, SMEMB);
    cudaFuncSetAttribute(k_tree,  cudaFuncAttributeMaxDynamicSharedMemorySize, SMEMB);
    cudaFuncSetAttribute(k_mlp0g, cudaFuncAttributeMaxDynamicSharedMemorySize, SMEMB);
    cudaFuncSetAttribute(k_mlp1g, cudaFuncAttributeMaxDynamicSharedMemorySize, SMEMB);
    attr_done = 1;
  }

  k_tok<<<1, 256>>>(x);
  launchP(k_prep, 512, 256, 0, x, emb, wih, whh, bih, bhh, lw, lb, rw, rb, l0w, l1w);
  launchP(k_epi, 64, 256, 0, -1);
  for (int t = 0; t < TSTEPS; t++){
    int m0p = 192 - 2*t; if (m0p < 0) m0p = 0;
    launchP(k_lstm, 128, 256, (size_t)SMEMB);
    launchP(k_point, 64, 256, 0, t, m0p, aw, ab);
    launchP(k_tree, 80, 256, (size_t)SMEMB);
    launchP(k_epi, 64, 256, 0, t);
  }
  launchP(k_mlp0g, 32, 256, (size_t)SMEMB);
  launchP(k_r0, 64, 256, 0, l0b);
  launchP(k_mlp1g, 128, 256, (size_t)SMEMB);
  launchP(k_r1, 64, 256, 0, l1b);
  launchP(k_mlp2, 64, 256, 0, l2w, l2b, out);
}